// round 16
// baseline (speedup 1.0000x reference)
#include <cuda_runtime.h>
#include <math.h>
#include <float.h>

// Geometry
#define NROWS   131072
#define KCODE   512
#define BCH     262144           // 64*64*64 batch stride in z (B,C,H,W)
#define TILEM   128
#define NTILES  1024             // NROWS / 128
#define GRID    148
#define TPB     512

// d_out layout (fp32, outputs concatenated)
#define OFF_LOSS 0
#define OFF_ZQ   1
#define OFF_PERP 8388609
#define OFF_ENC  8388610ULL
#define OFF_CODE 75497474ULL

// smem float offsets
#define S_ZTD   0        // [16384] z dup-pair: u64 ztd[p*256 + r*2 + e] = {v,v}, d=2p+e
#define S_WP    16384    // [32768] weight: wp[d*512 + c]
#define S_WN    49152    // [512]
#define S_ZN    49664    // [128]
#define S_PART  49792    // [1024f] = 512 u64: part[r*4 + wbit*2 + half]
#define S_CODE  50816    // [128] int
#define S_HIST  50944    // [512] int
#define S_LRED  51456    // [16]
#define S_FLAG  51472    // [1]
#define S_TOT   51480

__device__ float        g_loss_part[GRID];
__device__ int          g_hist_part[GRID * KCODE];
__device__ unsigned int g_done;   // zero-init; last block resets it

__device__ __forceinline__ unsigned long long packbb(float x) {
    unsigned long long r;
    asm("mov.b64 %0, {%1,%1};" : "=l"(r) : "f"(x));
    return r;
}
__device__ __forceinline__ void sts64(unsigned addr, unsigned long long v) {
    asm volatile("st.shared.u64 [%0], %1;" :: "r"(addr), "l"(v));
}
__device__ __forceinline__ void lds128(unsigned long long& a, unsigned long long& b,
                                       unsigned addr) {
    asm("ld.shared.v2.u64 {%0,%1}, [%2];" : "=l"(a), "=l"(b) : "r"(addr));
}
__device__ __forceinline__ unsigned long long lds64(unsigned addr) {
    unsigned long long v;
    asm("ld.shared.u64 %0, [%1];" : "=l"(v) : "r"(addr));
    return v;
}
__device__ __forceinline__ void ffma2(unsigned long long& acc,
                                      unsigned long long a, unsigned long long b) {
    asm("fma.rn.f32x2 %0, %1, %2, %0;" : "+l"(acc) : "l"(a), "l"(b));
}
__device__ __forceinline__ void unpack2(unsigned long long a, float& lo, float& hi) {
    asm("mov.b64 {%0,%1}, %2;" : "=f"(lo), "=f"(hi) : "l"(a));
}
__device__ __forceinline__ unsigned orderable(float s) {
    unsigned ub = __float_as_uint(s);
    return (ub & 0x80000000u) ? ~ub : (ub | 0x80000000u);
}

__global__ __launch_bounds__(TPB, 1)
void vq_fused(const float* __restrict__ z, const float* __restrict__ w,
              float* __restrict__ dout) {
    extern __shared__ float sm[];
    float*              ztf  = sm + S_ZTD;   // float view of ztd (low halves)
    float*              wp   = sm + S_WP;
    float*              wn   = sm + S_WN;
    float*              zn   = sm + S_ZN;
    unsigned long long* part = (unsigned long long*)(sm + S_PART);
    int*                rcd  = (int*)(sm + S_CODE);
    int*                hist = (int*)(sm + S_HIST);
    float*              lred = sm + S_LRED;
    unsigned*           sfin = (unsigned*)(sm + S_FLAG);

    const int tid  = threadIdx.x;
    const int wid  = tid >> 5;
    const int lane = tid & 31;
    const int n    = tid & 63;         // code-thread (0..63)
    const int mth  = tid >> 6;         // row-group thread (0..7), 8 rows per subtile
    const int wbit = (tid >> 5) & 1;

    // stage weight: wp[d*512 + c] = w[c*64 + d]
    for (int idx = tid; idx < 32768; idx += TPB) {
        int c = idx >> 6, d = idx & 63;
        wp[d * 512 + c] = w[idx];
    }
    hist[tid] = 0;
    __syncthreads();

    // wn[c]: strict sequential sum of rounded squares (reference order)
    {
        float v = wp[tid];
        float s = __fmul_rn(v, v);
#pragma unroll
        for (int d = 1; d < 64; ++d) {
            v = wp[d * 512 + tid];
            s = __fadd_rn(s, __fmul_rn(v, v));
        }
        wn[tid] = s;
    }

    const unsigned smbase = (unsigned)__cvta_generic_to_shared(sm);
    const unsigned ztb    = smbase + S_ZTD * 4;
    const unsigned wbB0   = smbase + S_WP * 4 + (unsigned)n * 8u;

    float ls = 0.0f;

    for (int tile = blockIdx.x; tile < NTILES; tile += GRID) {
        __syncthreads();   // protect ztd/rcd from previous tile epilogue
        const int    n0  = tile * TILEM;
        const int    b   = n0 >> 12;
        const int    rem = n0 & 4095;
        const float* zg  = z + (size_t)b * BCH + rem;

        // stage z dup-pair tile: ztd[(d>>1)*256 + r*2 + (d&1)] = {v,v}
#pragma unroll
        for (int pass = 0; pass < 16; ++pass) {
            int d = pass * 4 + (tid >> 7);
            int r = tid & 127;
            float v = zg[((size_t)d << 12) + r];
            sts64(ztb + (unsigned)((d >> 1) * 2048 + r * 16 + (d & 1) * 8),
                  packbb(v));
        }
        __syncthreads();

        // zn[r]: strict sequential (reference order); read low halves
        if (tid < 128) {
            float v = ztf[tid * 4];                    // d=0: (0*256 + r*2 + 0)*2
            float s = __fmul_rn(v, v);
#pragma unroll
            for (int d = 1; d < 64; ++d) {
                v = ztf[((d >> 1) * 256 + tid * 2 + (d & 1)) * 2];
                s = __fadd_rn(s, __fmul_rn(v, v));
            }
            zn[tid] = s;
        }
        __syncthreads();

        // ---- 2 row-subtiles x 2 code-halves: 8 rows x 2 code-pairs each ----
#pragma unroll
        for (int srow = 0; srow < 2; ++srow) {
            const unsigned zbA = ztb + (unsigned)(srow * 64 + mth * 8) * 16u;
#pragma unroll
            for (int half = 0; half < 2; ++half) {
                unsigned long long acc[16];
#pragma unroll
                for (int q = 0; q < 16; ++q) acc[q] = 0ULL;
                const unsigned wbH = wbB0 + (unsigned)half * 1024u;

#pragma unroll 4
                for (int p = 0; p < 32; ++p) {
                    unsigned long long za0[8], za1[8];
#pragma unroll
                    for (int i = 0; i < 8; ++i)
                        lds128(za0[i], za1[i],
                               zbA + (unsigned)p * 2048u + (unsigned)i * 16u);
                    const unsigned wa = wbH + (unsigned)p * 4096u;
                    unsigned long long w00 = lds64(wa);          // d=2p,   j=0
                    unsigned long long w01 = lds64(wa + 512u);   // d=2p,   j=1
                    unsigned long long w10 = lds64(wa + 2048u);  // d=2p+1, j=0
                    unsigned long long w11 = lds64(wa + 2560u);  // d=2p+1, j=1
#pragma unroll
                    for (int i = 0; i < 8; ++i) {
                        ffma2(acc[i * 2],     za0[i], w00);
                        ffma2(acc[i * 2],     za1[i], w10);
                        ffma2(acc[i * 2 + 1], za0[i], w01);
                        ffma2(acc[i * 2 + 1], za1[i], w11);
                    }
                }

                // epilogue: exact score pipeline + warp-reduced keys
#pragma unroll
                for (int i = 0; i < 8; ++i) {
                    const int r = srow * 64 + mth * 8 + i;
                    const float znr = zn[r];
                    unsigned long long key = 0xFFFFFFFFFFFFFFFFULL;
#pragma unroll
                    for (int j = 0; j < 2; ++j) {
                        float lo, hi;
                        unpack2(acc[i * 2 + j], lo, hi);
                        const int c0 = 2 * (n + 64 * j + 128 * half);
                        float s0 = __fsub_rn(__fadd_rn(znr, wn[c0]),
                                             __fadd_rn(lo, lo));
                        float s1 = __fsub_rn(__fadd_rn(znr, wn[c0 + 1]),
                                             __fadd_rn(hi, hi));
                        unsigned long long k0 =
                            ((unsigned long long)orderable(s0) << 32) | (unsigned)c0;
                        unsigned long long k1 =
                            ((unsigned long long)orderable(s1) << 32) | (unsigned)(c0 + 1);
                        if (k0 < key) key = k0;
                        if (k1 < key) key = k1;
                    }
#pragma unroll
                    for (int off = 16; off > 0; off >>= 1) {
                        unsigned long long o = __shfl_down_sync(0xFFFFFFFFu, key, off);
                        if (o < key) key = o;
                    }
                    if (lane == 0) part[r * 4 + wbit * 2 + half] = key;
                }
            }
        }
        __syncthreads();

        // merge 4 partials per row -> code
        if (tid < 128) {
            unsigned long long k  = part[tid * 4];
            unsigned long long o1 = part[tid * 4 + 1];
            unsigned long long o2 = part[tid * 4 + 2];
            unsigned long long o3 = part[tid * 4 + 3];
            if (o1 < k) k = o1;
            if (o2 < k) k = o2;
            if (o3 < k) k = o3;
            int code = (int)(unsigned)(k & 0xFFFFFFFFULL);
            rcd[tid] = code;
            dout[OFF_CODE + (size_t)(n0 + tid)] = (float)code;
            atomicAdd(&hist[code], 1);
        }
        __syncthreads();

        // zq + loss (coalesced by r)
        float* zqg = dout + OFF_ZQ + (size_t)b * BCH + rem;
#pragma unroll
        for (int pass = 0; pass < 16; ++pass) {
            int d  = pass * 4 + (tid >> 7);
            int rr = tid & 127;
            int code = rcd[rr];
            float zv = ztf[((d >> 1) * 256 + rr * 2 + (d & 1)) * 2];
            float wv = wp[d * 512 + code];
            float df = __fsub_rn(wv, zv);
            ls = fmaf(df, df, ls);
            zqg[((size_t)d << 12) + rr] = __fadd_rn(zv, df);
        }

        // encodings one-hot (float2, 8B-aligned region)
        float2* encp = (float2*)(dout + OFF_ENC);
#pragma unroll 8
        for (int pass = 0; pass < 64; ++pass) {
            int e  = pass * 512 + tid;
            int rr = e >> 8;
            int c2 = e & 255;
            int code = rcd[rr];
            float2 v = make_float2(0.0f, 0.0f);
            if (c2 == (code >> 1)) { if (code & 1) v.y = 1.0f; else v.x = 1.0f; }
            encp[(size_t)(n0 + rr) * 256 + c2] = v;
        }
    }

    // ---- per-block partials ----
    __syncthreads();
    float lw = ls;
#pragma unroll
    for (int off = 16; off > 0; off >>= 1)
        lw += __shfl_down_sync(0xFFFFFFFFu, lw, off);
    if (lane == 0) lred[wid] = lw;
    __syncthreads();
    if (tid == 0) {
        float t = 0.0f;
#pragma unroll
        for (int i = 0; i < 16; ++i) t += lred[i];
        g_loss_part[blockIdx.x] = t;
    }
    g_hist_part[blockIdx.x * KCODE + tid] = hist[tid];

    // ---- last-block finalize (graph-replay safe: resets g_done) ----
    __threadfence();
    if (tid == 0) *sfin = (atomicAdd(&g_done, 1u) == GRID - 1);
    __syncthreads();
    if (*sfin) {
        int cnt = 0;
        for (int bb = 0; bb < GRID; ++bb) cnt += g_hist_part[bb * KCODE + tid];
        float em = (float)cnt * (1.0f / 131072.0f);
        float v  = em * logf(__fadd_rn(em, 1e-10f));
#pragma unroll
        for (int off = 16; off > 0; off >>= 1)
            v += __shfl_down_sync(0xFFFFFFFFu, v, off);
        if (lane == 0) lred[wid] = v;
        __syncthreads();
        if (wid == 0) {
            float s = (lane < 16) ? lred[lane] : 0.0f;
#pragma unroll
            for (int off = 8; off > 0; off >>= 1)
                s += __shfl_down_sync(0xFFFFFFFFu, s, off);
            if (lane == 0) dout[OFF_PERP] = expf(-s);
        }
        if (wid == 1) {
            float s = 0.0f;
            for (int i = lane; i < GRID; i += 32) s += g_loss_part[i];
#pragma unroll
            for (int off = 16; off > 0; off >>= 1)
                s += __shfl_down_sync(0xFFFFFFFFu, s, off);
            if (lane == 0) {
                float m = s * (1.0f / 8388608.0f);
                dout[OFF_LOSS] = __fadd_rn(m, __fmul_rn(0.25f, m));
            }
        }
        __syncthreads();
        if (tid == 0) g_done = 0;
    }
}

extern "C" void kernel_launch(void* const* d_in, const int* in_sizes, int n_in,
                              void* d_out, int out_size) {
    const float* z = (const float*)d_in[0];
    const float* w = (const float*)d_in[1];
    float* out = (float*)d_out;

    cudaFuncSetAttribute(vq_fused, cudaFuncAttributeMaxDynamicSharedMemorySize,
                         S_TOT * 4);
    vq_fused<<<GRID, TPB, S_TOT * 4>>>(z, w, out);
}

// round 17
// speedup vs baseline: 1.1056x; 1.1056x over previous
#include <cuda_runtime.h>
#include <math.h>
#include <float.h>

// Geometry
#define NROWS   131072
#define KCODE   512
#define BCH     262144           // 64*64*64 batch stride in z (B,C,H,W)
#define TILEM   64
#define NTILES  2048             // NROWS / 64
#define GRID    148
#define TPB     512

// d_out layout (fp32, outputs concatenated)
#define OFF_LOSS 0
#define OFF_ZQ   1
#define OFF_PERP 8388609
#define OFF_ENC  8388610ULL
#define OFF_CODE 75497474ULL

// smem float offsets
#define S_ZT    0        // [4096]  z tile: zt[d*64 + r]
#define S_ZSW   4096     // [4096]  pair-swapped z: zsw[d*64 + r] = z[d][r^1]
#define S_WP    8192     // [32768] weight: wp[d*512 + c]
#define S_WN    40960    // [512]
#define S_ZN    41472    // [64]
#define S_PART  41536    // [256f] = 128 u64: part[r*2 + wbit]
#define S_CODE  41792    // [64] int
#define S_HIST  41856    // [512] int
#define S_LRED  42368    // [16]
#define S_FLAG  42384    // [1]
#define S_TOT   42392

__device__ float        g_loss_part[GRID];
__device__ int          g_hist_part[GRID * KCODE];
__device__ unsigned int g_done;   // zero-init; last block resets it

__device__ __forceinline__ void lds128(unsigned long long& a, unsigned long long& b,
                                       unsigned addr) {
    asm("ld.shared.v2.u64 {%0,%1}, [%2];" : "=l"(a), "=l"(b) : "r"(addr));
}
__device__ __forceinline__ void ffma2(unsigned long long& acc,
                                      unsigned long long a, unsigned long long b) {
    asm("fma.rn.f32x2 %0, %1, %2, %0;" : "+l"(acc) : "l"(a), "l"(b));
}
__device__ __forceinline__ void unpack2(unsigned long long a, float& lo, float& hi) {
    asm("mov.b64 {%0,%1}, %2;" : "=f"(lo), "=f"(hi) : "l"(a));
}
__device__ __forceinline__ unsigned orderable(float s) {
    unsigned ub = __float_as_uint(s);
    return (ub & 0x80000000u) ? ~ub : (ub | 0x80000000u);
}

__global__ __launch_bounds__(TPB, 1)
void vq_fused(const float* __restrict__ z, const float* __restrict__ w,
              float* __restrict__ dout) {
    extern __shared__ float sm[];
    float*              zt   = sm + S_ZT;
    float*              zsw  = sm + S_ZSW;
    float*              wp   = sm + S_WP;
    float*              wn   = sm + S_WN;
    float*              zn   = sm + S_ZN;
    unsigned long long* part = (unsigned long long*)(sm + S_PART);
    int*                rcd  = (int*)(sm + S_CODE);
    int*                hist = (int*)(sm + S_HIST);
    float*              lred = sm + S_LRED;
    unsigned*           sfin = (unsigned*)(sm + S_FLAG);

    const int tid  = threadIdx.x;
    const int wid  = tid >> 5;
    const int lane = tid & 31;
    const int n    = tid & 63;         // code-thread: codes 4n..4n+3, 4n+256..+259
    const int mg   = tid >> 6;         // row-group (0..7), rows mg*8..mg*8+7
    const int wbit = (tid >> 5) & 1;

    // stage weight: wp[d*512 + c] = w[c*64 + d]
    for (int idx = tid; idx < 32768; idx += TPB) {
        int c = idx >> 6, d = idx & 63;
        wp[d * 512 + c] = w[idx];
    }
    hist[tid] = 0;
    __syncthreads();

    // wn[c]: strict sequential sum of rounded squares (reference order)
    {
        float v = wp[tid];
        float s = __fmul_rn(v, v);
#pragma unroll
        for (int d = 1; d < 64; ++d) {
            v = wp[d * 512 + tid];
            s = __fadd_rn(s, __fmul_rn(v, v));
        }
        wn[tid] = s;
    }

    const unsigned smbase = (unsigned)__cvta_generic_to_shared(sm);
    const unsigned zA  = smbase + S_ZT * 4 + (unsigned)mg * 32u;   // + d*256
    const unsigned zSA = smbase + S_ZSW * 4 + (unsigned)mg * 32u;
    const unsigned wB  = smbase + S_WP * 4 + (unsigned)n * 16u;    // + d*2048 (+1024)

    float ls = 0.0f;

    for (int tile = blockIdx.x; tile < NTILES; tile += GRID) {
        __syncthreads();   // protect zt/rcd from previous tile epilogue
        const int    n0  = tile * TILEM;
        const int    b   = n0 >> 12;
        const int    rem = n0 & 4095;
        const float* zg  = z + (size_t)b * BCH + rem;

        // stage z tile (64 rows x 64 dims): normal + pair-swapped copies
#pragma unroll
        for (int pass = 0; pass < 8; ++pass) {
            int d = pass * 8 + mg;
            int r = n;
            float v = zg[((size_t)d << 12) + r];
            zt[d * 64 + r]        = v;
            zsw[d * 64 + (r ^ 1)] = v;
        }
        __syncthreads();

        // zn[r]: strict sequential (reference order)
        if (tid < 64) {
            float v = zt[tid];
            float s = __fmul_rn(v, v);
#pragma unroll
            for (int d = 1; d < 64; ++d) {
                v = zt[d * 64 + tid];
                s = __fadd_rn(s, __fmul_rn(v, v));
            }
            zn[tid] = s;
        }
        __syncthreads();

        // ---- main GEMM: diagonal-lane f32x2, exact sequential chains ----
        // accD[q][g*2+u] lanes = dots (2q, c), (2q+1, c+1);  c = 4n + 2u + 256g
        // accA[q][g*2+u] lanes = dots (2q+1, c), (2q, c+1)
        unsigned long long accD[16], accA[16];
#pragma unroll
        for (int q = 0; q < 16; ++q) { accD[q] = 0ULL; accA[q] = 0ULL; }

#pragma unroll 4
        for (int d = 0; d < 64; ++d) {
            unsigned long long za0, za1, za2, za3, zs0, zs1, zs2, zs3;
            const unsigned zo = (unsigned)d * 256u;
            lds128(za0, za1, zA + zo);
            lds128(za2, za3, zA + zo + 16u);
            lds128(zs0, zs1, zSA + zo);
            lds128(zs2, zs3, zSA + zo + 16u);
            unsigned long long w00, w01, w10, w11;
            const unsigned wo = wB + (unsigned)d * 2048u;
            lds128(w00, w01, wo);            // codes 4n..4n+3
            lds128(w10, w11, wo + 1024u);    // codes 4n+256..4n+259
#pragma unroll
            for (int q = 0; q < 4; ++q) {
                unsigned long long a = (q == 0) ? za0 : (q == 1) ? za1 : (q == 2) ? za2 : za3;
                unsigned long long s = (q == 0) ? zs0 : (q == 1) ? zs1 : (q == 2) ? zs2 : zs3;
                ffma2(accD[q * 4 + 0], a, w00);
                ffma2(accD[q * 4 + 1], a, w01);
                ffma2(accD[q * 4 + 2], a, w10);
                ffma2(accD[q * 4 + 3], a, w11);
                ffma2(accA[q * 4 + 0], s, w00);
                ffma2(accA[q * 4 + 1], s, w01);
                ffma2(accA[q * 4 + 2], s, w10);
                ffma2(accA[q * 4 + 3], s, w11);
            }
        }

        // ---- epilogue: exact score pipeline + per-row keys ----
#pragma unroll
        for (int q = 0; q < 4; ++q) {
            const int   re  = mg * 8 + 2 * q;       // even row
            const float znE = zn[re];
            const float znO = zn[re + 1];
            unsigned long long keyE = 0xFFFFFFFFFFFFFFFFULL;
            unsigned long long keyO = 0xFFFFFFFFFFFFFFFFULL;
#pragma unroll
            for (int gu = 0; gu < 4; ++gu) {
                const int c0 = 4 * n + 2 * (gu & 1) + 256 * (gu >> 1);
                float d0, d1, a0, a1;
                unpack2(accD[q * 4 + gu], d0, d1);  // (re,c0) (re+1,c0+1)
                unpack2(accA[q * 4 + gu], a0, a1);  // (re+1,c0) (re,c0+1)
                float sE0 = __fsub_rn(__fadd_rn(znE, wn[c0]),     __fadd_rn(d0, d0));
                float sE1 = __fsub_rn(__fadd_rn(znE, wn[c0 + 1]), __fadd_rn(a1, a1));
                float sO0 = __fsub_rn(__fadd_rn(znO, wn[c0]),     __fadd_rn(a0, a0));
                float sO1 = __fsub_rn(__fadd_rn(znO, wn[c0 + 1]), __fadd_rn(d1, d1));
                unsigned long long kE0 = ((unsigned long long)orderable(sE0) << 32) | (unsigned)c0;
                unsigned long long kE1 = ((unsigned long long)orderable(sE1) << 32) | (unsigned)(c0 + 1);
                unsigned long long kO0 = ((unsigned long long)orderable(sO0) << 32) | (unsigned)c0;
                unsigned long long kO1 = ((unsigned long long)orderable(sO1) << 32) | (unsigned)(c0 + 1);
                if (kE0 < keyE) keyE = kE0;
                if (kE1 < keyE) keyE = kE1;
                if (kO0 < keyO) keyO = kO0;
                if (kO1 < keyO) keyO = kO1;
            }
#pragma unroll
            for (int off = 16; off > 0; off >>= 1) {
                unsigned long long oE = __shfl_down_sync(0xFFFFFFFFu, keyE, off);
                unsigned long long oO = __shfl_down_sync(0xFFFFFFFFu, keyO, off);
                if (oE < keyE) keyE = oE;
                if (oO < keyO) keyO = oO;
            }
            if (lane == 0) {
                part[(re)     * 2 + wbit] = keyE;
                part[(re + 1) * 2 + wbit] = keyO;
            }
        }
        __syncthreads();

        // merge 2 partials per row -> code
        if (tid < 64) {
            unsigned long long k  = part[tid * 2];
            unsigned long long o1 = part[tid * 2 + 1];
            if (o1 < k) k = o1;
            int code = (int)(unsigned)(k & 0xFFFFFFFFULL);
            rcd[tid] = code;
            dout[OFF_CODE + (size_t)(n0 + tid)] = (float)code;
            atomicAdd(&hist[code], 1);
        }
        __syncthreads();

        // zq + loss (coalesced by r)
        float* zqg = dout + OFF_ZQ + (size_t)b * BCH + rem;
#pragma unroll
        for (int pass = 0; pass < 8; ++pass) {
            int d  = pass * 8 + mg;
            int rr = n;
            int code = rcd[rr];
            float zv = zt[d * 64 + rr];
            float wv = wp[d * 512 + code];
            float df = __fsub_rn(wv, zv);
            ls = fmaf(df, df, ls);
            zqg[((size_t)d << 12) + rr] = __fadd_rn(zv, df);
        }

        // encodings one-hot (float2, 8B-aligned region)
        float2* encp = (float2*)(dout + OFF_ENC);
#pragma unroll 8
        for (int pass = 0; pass < 32; ++pass) {
            int e  = pass * 512 + tid;
            int rr = e >> 8;
            int c2 = e & 255;
            int code = rcd[rr];
            float2 v = make_float2(0.0f, 0.0f);
            if (c2 == (code >> 1)) { if (code & 1) v.y = 1.0f; else v.x = 1.0f; }
            encp[(size_t)(n0 + rr) * 256 + c2] = v;
        }
    }

    // ---- per-block partials ----
    __syncthreads();
    float lw = ls;
#pragma unroll
    for (int off = 16; off > 0; off >>= 1)
        lw += __shfl_down_sync(0xFFFFFFFFu, lw, off);
    if (lane == 0) lred[wid] = lw;
    __syncthreads();
    if (tid == 0) {
        float t = 0.0f;
#pragma unroll
        for (int i = 0; i < 16; ++i) t += lred[i];
        g_loss_part[blockIdx.x] = t;
    }
    g_hist_part[blockIdx.x * KCODE + tid] = hist[tid];

    // ---- last-block finalize (graph-replay safe: resets g_done) ----
    __threadfence();
    if (tid == 0) *sfin = (atomicAdd(&g_done, 1u) == GRID - 1);
    __syncthreads();
    if (*sfin) {
        int cnt = 0;
        for (int bb = 0; bb < GRID; ++bb) cnt += g_hist_part[bb * KCODE + tid];
        float em = (float)cnt * (1.0f / 131072.0f);
        float v  = em * logf(__fadd_rn(em, 1e-10f));
#pragma unroll
        for (int off = 16; off > 0; off >>= 1)
            v += __shfl_down_sync(0xFFFFFFFFu, v, off);
        if (lane == 0) lred[wid] = v;
        __syncthreads();
        if (wid == 0) {
            float s = (lane < 16) ? lred[lane] : 0.0f;
#pragma unroll
            for (int off = 8; off > 0; off >>= 1)
                s += __shfl_down_sync(0xFFFFFFFFu, s, off);
            if (lane == 0) dout[OFF_PERP] = expf(-s);
        }
        if (wid == 1) {
            float s = 0.0f;
            for (int i = lane; i < GRID; i += 32) s += g_loss_part[i];
#pragma unroll
            for (int off = 16; off > 0; off >>= 1)
                s += __shfl_down_sync(0xFFFFFFFFu, s, off);
            if (lane == 0) {
                float m = s * (1.0f / 8388608.0f);
                dout[OFF_LOSS] = __fadd_rn(m, __fmul_rn(0.25f, m));
            }
        }
        __syncthreads();
        if (tid == 0) g_done = 0;
    }
}

extern "C" void kernel_launch(void* const* d_in, const int* in_sizes, int n_in,
                              void* d_out, int out_size) {
    const float* z = (const float*)d_in[0];
    const float* w = (const float*)d_in[1];
    float* out = (float*)d_out;

    cudaFuncSetAttribute(vq_fused, cudaFuncAttributeMaxDynamicSharedMemorySize,
                         S_TOT * 4);
    vq_fused<<<GRID, TPB, S_TOT * 4>>>(z, w, out);
}